// round 1
// baseline (speedup 1.0000x reference)
#include <cuda_runtime.h>
#include <math.h>

// Shapes (fixed by the problem)
#define NB 128   // windows (batch)
#define NN 256   // tokens per window (wh*ww = 8*32)
#define NC 512   // channels
#define NH 16    // heads
#define HD 32    // head dim
#define WW 32    // window width
#define QSCALE 0.17677669529663687f  // 1/sqrt(32)

// GEMM tiling
#define BM 128
#define BN 128
#define BK 16

// Scratch (device globals — no allocation allowed)
__device__ float g_Q[(size_t)NB * NH * NN * HD];      // 64 MB, pre-scaled by QSCALE
__device__ float g_K[(size_t)NB * NH * NN * HD];      // 64 MB
__device__ float g_V[(size_t)NB * NH * NN * HD];      // 64 MB
__device__ float g_biasT[(size_t)NH * NN * NN];       // 4 MB, [h][m][n]
__device__ float g_AO[(size_t)NB * NN * NC];          // 64 MB, attention out [B,N,C]

// ---------------------------------------------------------------------------
// Bias precompute: g_biasT[h][m][n] = rpb_table[idx(n,m)][h]
// idx(n,m) = (rn-rm+7)*63 + (cn-cm+31), r=tok/32, c=tok%32
// ---------------------------------------------------------------------------
__global__ void bias_kernel(const float* __restrict__ rpb) {
    int idx = blockIdx.x * blockDim.x + threadIdx.x;   // h*65536 + m*256 + n
    int n = idx & 255;
    int m = (idx >> 8) & 255;
    int h = idx >> 16;
    int t = ((n >> 5) - (m >> 5) + 7) * 63 + ((n & 31) - (m & 31) + 31);
    g_biasT[idx] = rpb[t * NH + h];
}

// ---------------------------------------------------------------------------
// QKV GEMM: qkv[i,j] = sum_k x[i,k]*qkv_w[j,k] + qkv_b[j]
// M=32768, Nout=1536, K=512. Scatter epilogue into g_Q/g_K/g_V [B,H,N,hd].
// ---------------------------------------------------------------------------
__global__ __launch_bounds__(256) void qkv_gemm(const float* __restrict__ A,
                                                const float* __restrict__ W,
                                                const float* __restrict__ bias) {
    __shared__ float As[BK][BM];
    __shared__ float Bs[BK][BN];
    int tid = threadIdx.x;
    int row0 = blockIdx.y * BM;
    int col0 = blockIdx.x * BN;
    int tx = tid & 15, ty = tid >> 4;

    float acc[8][8];
#pragma unroll
    for (int i = 0; i < 8; i++)
#pragma unroll
        for (int j = 0; j < 8; j++) acc[i][j] = 0.0f;

    for (int k0 = 0; k0 < NC; k0 += BK) {
#pragma unroll
        for (int i = 0; i < 2; i++) {
            int id = tid + i * 256;
            int r = id >> 2, cg = id & 3;
            float4 va = *(const float4*)(A + (size_t)(row0 + r) * NC + k0 + cg * 4);
            As[cg * 4 + 0][r] = va.x; As[cg * 4 + 1][r] = va.y;
            As[cg * 4 + 2][r] = va.z; As[cg * 4 + 3][r] = va.w;
            float4 vb = *(const float4*)(W + (size_t)(col0 + r) * NC + k0 + cg * 4);
            Bs[cg * 4 + 0][r] = vb.x; Bs[cg * 4 + 1][r] = vb.y;
            Bs[cg * 4 + 2][r] = vb.z; Bs[cg * 4 + 3][r] = vb.w;
        }
        __syncthreads();
#pragma unroll
        for (int kk = 0; kk < BK; kk++) {
            float a[8], b[8];
            *(float4*)&a[0] = *(const float4*)&As[kk][ty * 8];
            *(float4*)&a[4] = *(const float4*)&As[kk][ty * 8 + 4];
            *(float4*)&b[0] = *(const float4*)&Bs[kk][tx * 8];
            *(float4*)&b[4] = *(const float4*)&Bs[kk][tx * 8 + 4];
#pragma unroll
            for (int i = 0; i < 8; i++)
#pragma unroll
                for (int j = 0; j < 8; j++) acc[i][j] += a[i] * b[j];
        }
        __syncthreads();
    }

    // Epilogue: which = q/k/v is uniform per block (tile never straddles 512)
    int which = col0 >> 9;
    float* dst = (which == 0) ? g_Q : ((which == 1) ? g_K : g_V);
    float qs = (which == 0) ? QSCALE : 1.0f;
#pragma unroll
    for (int i = 0; i < 8; i++) {
        int gi = row0 + ty * 8 + i;
        int bb = gi >> 8, n = gi & 255;
#pragma unroll
        for (int j = 0; j < 8; j++) {
            int gj = col0 + tx * 8 + j;
            float v = (acc[i][j] + bias[gj]) * qs;
            int cc = gj & 511;
            int h = cc >> 5, d = cc & 31;
            dst[(((size_t)bb * NH + h) * NN + n) * HD + d] = v;
        }
    }
}

// ---------------------------------------------------------------------------
// Attention: one CTA per (b,h). K,V in smem (64KB). Thread n owns query row n,
// single-pass online softmax over 256 keys. Writes g_AO in [B,N,C] layout.
// ---------------------------------------------------------------------------
__global__ __launch_bounds__(256) void attn_kernel() {
    extern __shared__ float sm[];
    float* Ks = sm;            // 8192 floats
    float* Vs = sm + NN * HD;  // 8192 floats

    int bh = blockIdx.x;           // b*16 + h
    int b = bh >> 4, h = bh & 15;
    int tid = threadIdx.x;

    size_t base = (size_t)bh * NN * HD;
    const float4* K4 = (const float4*)(g_K + base);
    const float4* V4 = (const float4*)(g_V + base);
    float4* Ks4 = (float4*)Ks;
    float4* Vs4 = (float4*)Vs;
#pragma unroll
    for (int i = 0; i < 8; i++) {
        Ks4[tid + i * 256] = K4[tid + i * 256];
        Vs4[tid + i * 256] = V4[tid + i * 256];
    }

    float4 q[8];
    const float4* Qp = (const float4*)(g_Q + base + (size_t)tid * HD);
#pragma unroll
    for (int i = 0; i < 8; i++) q[i] = Qp[i];
    __syncthreads();

    const float* bT = g_biasT + (size_t)h * NN * NN + tid;  // + m*256

    float mx = -1e30f, l = 0.0f;
    float4 acc[8];
#pragma unroll
    for (int i = 0; i < 8; i++) acc[i] = make_float4(0.f, 0.f, 0.f, 0.f);

    for (int m0 = 0; m0 < NN; m0 += 4) {
        float bvals[4];
#pragma unroll
        for (int j = 0; j < 4; j++) bvals[j] = bT[(m0 + j) * NN];
#pragma unroll
        for (int j = 0; j < 4; j++) {
            int m = m0 + j;
            const float4* kr = (const float4*)(Ks + m * HD);
            float dot = 0.0f;
#pragma unroll
            for (int i = 0; i < 8; i++) {
                float4 kv = kr[i];
                dot += q[i].x * kv.x + q[i].y * kv.y + q[i].z * kv.z + q[i].w * kv.w;
            }
            float s = dot + bvals[j];
            float p;
            if (s > mx) {
                float corr = __expf(mx - s);
                l *= corr;
#pragma unroll
                for (int i = 0; i < 8; i++) {
                    acc[i].x *= corr; acc[i].y *= corr;
                    acc[i].z *= corr; acc[i].w *= corr;
                }
                mx = s;
                p = 1.0f;
            } else {
                p = __expf(s - mx);
            }
            l += p;
            const float4* vr = (const float4*)(Vs + m * HD);
#pragma unroll
            for (int i = 0; i < 8; i++) {
                float4 vv = vr[i];
                acc[i].x += p * vv.x; acc[i].y += p * vv.y;
                acc[i].z += p * vv.z; acc[i].w += p * vv.w;
            }
        }
    }

    float inv = 1.0f / l;
    float4* Op = (float4*)(g_AO + ((size_t)(b * NN + tid)) * NC + h * HD);
#pragma unroll
    for (int i = 0; i < 8; i++) {
        float4 o = acc[i];
        o.x *= inv; o.y *= inv; o.z *= inv; o.w *= inv;
        Op[i] = o;
    }
}

// ---------------------------------------------------------------------------
// Proj GEMM: out[i,j] = sum_k g_AO[i,k]*proj_w[j,k] + proj_b[j]
// M=32768, Nout=512, K=512.
// ---------------------------------------------------------------------------
__global__ __launch_bounds__(256) void proj_gemm(const float* __restrict__ W,
                                                 const float* __restrict__ bias,
                                                 float* __restrict__ out) {
    __shared__ float As[BK][BM];
    __shared__ float Bs[BK][BN];
    int tid = threadIdx.x;
    int row0 = blockIdx.y * BM;
    int col0 = blockIdx.x * BN;
    int tx = tid & 15, ty = tid >> 4;
    const float* A = g_AO;

    float acc[8][8];
#pragma unroll
    for (int i = 0; i < 8; i++)
#pragma unroll
        for (int j = 0; j < 8; j++) acc[i][j] = 0.0f;

    for (int k0 = 0; k0 < NC; k0 += BK) {
#pragma unroll
        for (int i = 0; i < 2; i++) {
            int id = tid + i * 256;
            int r = id >> 2, cg = id & 3;
            float4 va = *(const float4*)(A + (size_t)(row0 + r) * NC + k0 + cg * 4);
            As[cg * 4 + 0][r] = va.x; As[cg * 4 + 1][r] = va.y;
            As[cg * 4 + 2][r] = va.z; As[cg * 4 + 3][r] = va.w;
            float4 vb = *(const float4*)(W + (size_t)(col0 + r) * NC + k0 + cg * 4);
            Bs[cg * 4 + 0][r] = vb.x; Bs[cg * 4 + 1][r] = vb.y;
            Bs[cg * 4 + 2][r] = vb.z; Bs[cg * 4 + 3][r] = vb.w;
        }
        __syncthreads();
#pragma unroll
        for (int kk = 0; kk < BK; kk++) {
            float a[8], b[8];
            *(float4*)&a[0] = *(const float4*)&As[kk][ty * 8];
            *(float4*)&a[4] = *(const float4*)&As[kk][ty * 8 + 4];
            *(float4*)&b[0] = *(const float4*)&Bs[kk][tx * 8];
            *(float4*)&b[4] = *(const float4*)&Bs[kk][tx * 8 + 4];
#pragma unroll
            for (int i = 0; i < 8; i++)
#pragma unroll
                for (int j = 0; j < 8; j++) acc[i][j] += a[i] * b[j];
        }
        __syncthreads();
    }

#pragma unroll
    for (int i = 0; i < 8; i++) {
        int gi = row0 + ty * 8 + i;
        float4 o0, o1;
        int j0 = col0 + tx * 8;
        o0.x = acc[i][0] + bias[j0 + 0]; o0.y = acc[i][1] + bias[j0 + 1];
        o0.z = acc[i][2] + bias[j0 + 2]; o0.w = acc[i][3] + bias[j0 + 3];
        o1.x = acc[i][4] + bias[j0 + 4]; o1.y = acc[i][5] + bias[j0 + 5];
        o1.z = acc[i][6] + bias[j0 + 6]; o1.w = acc[i][7] + bias[j0 + 7];
        *(float4*)(out + (size_t)gi * NC + j0) = o0;
        *(float4*)(out + (size_t)gi * NC + j0 + 4) = o1;
    }
}

// ---------------------------------------------------------------------------
extern "C" void kernel_launch(void* const* d_in, const int* in_sizes, int n_in,
                              void* d_out, int out_size) {
    const float* x      = (const float*)d_in[0];
    // d_in[1] = q_global (unused by reference)
    const float* qkv_w  = (const float*)d_in[2];
    const float* qkv_b  = (const float*)d_in[3];
    const float* proj_w = (const float*)d_in[4];
    const float* proj_b = (const float*)d_in[5];
    const float* rpb    = (const float*)d_in[6];
    float* out = (float*)d_out;

    // bias table -> [H][m][n]
    bias_kernel<<<(NH * NN * NN) / 256, 256>>>(rpb);

    // QKV: M=32768 (256 tiles), Nout=1536 (12 tiles)
    qkv_gemm<<<dim3(1536 / BN, (NB * NN) / BM), 256>>>(x, qkv_w, qkv_b);

    // Attention: 2048 CTAs, 64KB dynamic smem
    cudaFuncSetAttribute(attn_kernel, cudaFuncAttributeMaxDynamicSharedMemorySize,
                         2 * NN * HD * sizeof(float));
    attn_kernel<<<NB * NH, 256, 2 * NN * HD * sizeof(float)>>>();

    // Proj: M=32768 (256 tiles), Nout=512 (4 tiles)
    proj_gemm<<<dim3(NC / BN, (NB * NN) / BM), 256>>>(proj_w, proj_b, out);
}

// round 3
// speedup vs baseline: 1.7769x; 1.7769x over previous
#include <cuda_runtime.h>
#include <cstdint>
#include <math.h>

// Shapes (fixed)
#define NB 128
#define NN 256
#define NC 512
#define NH 16
#define HD 32
#define QSCALE 0.17677669529663687f  // 1/sqrt(32)

// GEMM tiling
#define BM 128
#define BN 128
#define BK 16
#define KSTRIDE 20               // BK + 4 pad (floats) -> conflict-free frags
#define ABUF_FLOATS (BM * KSTRIDE)   // 2560
#define GEMM_SMEM (4 * ABUF_FLOATS * 4)  // A0,A1,B0,B1 = 40960 B

// Scratch (device globals — no allocation allowed)
__device__ float g_Q[(size_t)NB * NH * NN * HD];
__device__ float g_K[(size_t)NB * NH * NN * HD];
__device__ float g_V[(size_t)NB * NH * NN * HD];
__device__ float g_biasT[(size_t)NH * NN * NN];
__device__ float g_AO[(size_t)NB * NN * NC];

__device__ __forceinline__ uint32_t cvt_tf32(float f) {
    uint32_t u;
    asm("cvt.rna.tf32.f32 %0, %1;" : "=r"(u) : "f"(f));
    return u;
}

__device__ __forceinline__ void mma_tf32(float* d, const uint32_t* a, const uint32_t* b) {
    asm volatile(
        "mma.sync.aligned.m16n8k8.row.col.f32.tf32.tf32.f32 "
        "{%0,%1,%2,%3}, {%4,%5,%6,%7}, {%8,%9}, {%0,%1,%2,%3};"
        : "+f"(d[0]), "+f"(d[1]), "+f"(d[2]), "+f"(d[3])
        : "r"(a[0]), "r"(a[1]), "r"(a[2]), "r"(a[3]), "r"(b[0]), "r"(b[1]));
}

// ---------------------------------------------------------------------------
// Bias precompute: g_biasT[h][m][n] = rpb_table[idx(n,m)][h]
// ---------------------------------------------------------------------------
__global__ void bias_kernel(const float* __restrict__ rpb) {
    int idx = blockIdx.x * blockDim.x + threadIdx.x;
    int n = idx & 255;
    int m = (idx >> 8) & 255;
    int h = idx >> 16;
    int t = ((n >> 5) - (m >> 5) + 7) * 63 + ((n & 31) - (m & 31) + 31);
    g_biasT[idx] = rpb[t * NH + h];
}

// ---------------------------------------------------------------------------
// tf32 mma.sync GEMM: D[m][n] = sum_k A[m][k]*W[n][k]   (both K-major)
// mode 0: qkv epilogue (scatter to g_Q/g_K/g_V, fold QSCALE into Q)
// mode 1: proj epilogue (row-major out)
// ---------------------------------------------------------------------------
__global__ __launch_bounds__(256, 2) void mma_gemm(const float* __restrict__ Ain,
                                                   const float* __restrict__ W,
                                                   const float* __restrict__ bias,
                                                   int mode, float* __restrict__ out) {
    extern __shared__ float sm[];
    // buffers: A(p) = sm + p*ABUF, B(p) = sm + 2*ABUF + p*ABUF
    const float* A = Ain ? Ain : (const float*)g_AO;

    int tid = threadIdx.x;
    int wid = tid >> 5;
    int lane = tid & 31;
    int wr = wid >> 2;        // 0..1  (64-row group)
    int wc = wid & 3;         // 0..3  (32-col group)
    int lr = lane >> 2;       // 0..7
    int lc = lane & 3;        // 0..3

    int row0 = blockIdx.y * BM;
    int col0 = blockIdx.x * BN;

    // ldg indices: 512 float4 per matrix per chunk; this thread owns idx, idx+256
    int r_g = tid >> 2;       // 0..63 (then +64)
    int c4_g = tid & 3;       // 0..3
    const float4* Ag0 = (const float4*)(A + (size_t)(row0 + r_g) * NC) + c4_g;
    const float4* Ag1 = (const float4*)(A + (size_t)(row0 + r_g + 64) * NC) + c4_g;
    const float4* Bg0 = (const float4*)(W + (size_t)(col0 + r_g) * NC) + c4_g;
    const float4* Bg1 = (const float4*)(W + (size_t)(col0 + r_g + 64) * NC) + c4_g;

    float acc[4][4][4];
#pragma unroll
    for (int i = 0; i < 4; i++)
#pragma unroll
        for (int j = 0; j < 4; j++)
#pragma unroll
            for (int k = 0; k < 4; k++) acc[i][j][k] = 0.0f;

    float4 ra0, ra1, rb0, rb1;
    // prologue: chunk 0
    ra0 = Ag0[0]; ra1 = Ag1[0]; rb0 = Bg0[0]; rb1 = Bg1[0];

    const int NCH = NC / BK;  // 32
#pragma unroll 1
    for (int c = 0; c < NCH; c++) {
        int cur = c & 1;
        // STS current regs -> buffer cur (first iter: prologue data)
        {
            float* As = sm + cur * ABUF_FLOATS;
            float* Bs = sm + 2 * ABUF_FLOATS + cur * ABUF_FLOATS;
            uint4 u;
            u = make_uint4(cvt_tf32(ra0.x), cvt_tf32(ra0.y), cvt_tf32(ra0.z), cvt_tf32(ra0.w));
            *(uint4*)(As + r_g * KSTRIDE + c4_g * 4) = u;
            u = make_uint4(cvt_tf32(ra1.x), cvt_tf32(ra1.y), cvt_tf32(ra1.z), cvt_tf32(ra1.w));
            *(uint4*)(As + (r_g + 64) * KSTRIDE + c4_g * 4) = u;
            u = make_uint4(cvt_tf32(rb0.x), cvt_tf32(rb0.y), cvt_tf32(rb0.z), cvt_tf32(rb0.w));
            *(uint4*)(Bs + r_g * KSTRIDE + c4_g * 4) = u;
            u = make_uint4(cvt_tf32(rb1.x), cvt_tf32(rb1.y), cvt_tf32(rb1.z), cvt_tf32(rb1.w));
            *(uint4*)(Bs + (r_g + 64) * KSTRIDE + c4_g * 4) = u;
        }
        // LDG next chunk
        if (c + 1 < NCH) {
            int ko = (c + 1) * (BK / 4);
            ra0 = Ag0[ko]; ra1 = Ag1[ko]; rb0 = Bg0[ko]; rb1 = Bg1[ko];
        }
        __syncthreads();
        // MMA over buffer cur: 2 ksteps of 8
        {
            const uint32_t* As = (const uint32_t*)(sm + cur * ABUF_FLOATS);
            const uint32_t* Bs = (const uint32_t*)(sm + 2 * ABUF_FLOATS + cur * ABUF_FLOATS);
#pragma unroll
            for (int ks = 0; ks < 2; ks++) {
                int k0 = ks * 8;
                uint32_t af[4][4], bf[4][2];
#pragma unroll
                for (int mt = 0; mt < 4; mt++) {
                    int r0 = wr * 64 + mt * 16 + lr;
                    af[mt][0] = As[r0 * KSTRIDE + k0 + lc];
                    af[mt][1] = As[(r0 + 8) * KSTRIDE + k0 + lc];
                    af[mt][2] = As[r0 * KSTRIDE + k0 + lc + 4];
                    af[mt][3] = As[(r0 + 8) * KSTRIDE + k0 + lc + 4];
                }
#pragma unroll
                for (int nt = 0; nt < 4; nt++) {
                    int n0 = wc * 32 + nt * 8 + lr;
                    bf[nt][0] = Bs[n0 * KSTRIDE + k0 + lc];
                    bf[nt][1] = Bs[n0 * KSTRIDE + k0 + lc + 4];
                }
#pragma unroll
                for (int mt = 0; mt < 4; mt++)
#pragma unroll
                    for (int nt = 0; nt < 4; nt++)
                        mma_tf32(acc[mt][nt], af[mt], bf[nt]);
            }
        }
        __syncthreads();
    }

    // -------------------------- epilogue --------------------------
    int colw = col0 + wc * 32;         // warp's 32-col group (one head in mode 0)
    // bias for this thread's columns: nt*8 + 2*lc, +1
    float bv[4][2];
#pragma unroll
    for (int nt = 0; nt < 4; nt++) {
        bv[nt][0] = bias[colw + nt * 8 + 2 * lc];
        bv[nt][1] = bias[colw + nt * 8 + 2 * lc + 1];
    }

    if (mode == 0) {
        int which = colw >> 9;
        float* dst = (which == 0) ? g_Q : ((which == 1) ? g_K : g_V);
        float qs = (which == 0) ? QSCALE : 1.0f;
        int h = (colw & 511) >> 5;
#pragma unroll
        for (int mt = 0; mt < 4; mt++) {
            int gr0 = row0 + wr * 64 + mt * 16 + lr;
            int b0i = gr0 >> 8, n0i = gr0 & 255;
            int gr1 = gr0 + 8;
            int b1i = gr1 >> 8, n1i = gr1 & 255;
            float* p0 = dst + (((size_t)b0i * NH + h) * NN + n0i) * HD;
            float* p1 = dst + (((size_t)b1i * NH + h) * NN + n1i) * HD;
#pragma unroll
            for (int nt = 0; nt < 4; nt++) {
                int d = nt * 8 + 2 * lc;
                float2 v0 = make_float2((acc[mt][nt][0] + bv[nt][0]) * qs,
                                        (acc[mt][nt][1] + bv[nt][1]) * qs);
                float2 v1 = make_float2((acc[mt][nt][2] + bv[nt][0]) * qs,
                                        (acc[mt][nt][3] + bv[nt][1]) * qs);
                *(float2*)(p0 + d) = v0;
                *(float2*)(p1 + d) = v1;
            }
        }
    } else {
#pragma unroll
        for (int mt = 0; mt < 4; mt++) {
            int gr0 = row0 + wr * 64 + mt * 16 + lr;
            float* p0 = out + (size_t)gr0 * NC + colw;
            float* p1 = out + (size_t)(gr0 + 8) * NC + colw;
#pragma unroll
            for (int nt = 0; nt < 4; nt++) {
                int d = nt * 8 + 2 * lc;
                *(float2*)(p0 + d) = make_float2(acc[mt][nt][0] + bv[nt][0],
                                                 acc[mt][nt][1] + bv[nt][1]);
                *(float2*)(p1 + d) = make_float2(acc[mt][nt][2] + bv[nt][0],
                                                 acc[mt][nt][3] + bv[nt][1]);
            }
        }
    }
}

// ---------------------------------------------------------------------------
// Attention: one CTA per (b,h), thread = query row, online softmax
// ---------------------------------------------------------------------------
__global__ __launch_bounds__(256) void attn_kernel() {
    extern __shared__ float smatt[];
    float* Ks = smatt;
    float* Vs = smatt + NN * HD;

    int bh = blockIdx.x;
    int b = bh >> 4, h = bh & 15;
    int tid = threadIdx.x;

    size_t base = (size_t)bh * NN * HD;
    const float4* K4 = (const float4*)(g_K + base);
    const float4* V4 = (const float4*)(g_V + base);
    float4* Ks4 = (float4*)Ks;
    float4* Vs4 = (float4*)Vs;
#pragma unroll
    for (int i = 0; i < 8; i++) {
        Ks4[tid + i * 256] = K4[tid + i * 256];
        Vs4[tid + i * 256] = V4[tid + i * 256];
    }

    float4 q[8];
    const float4* Qp = (const float4*)(g_Q + base + (size_t)tid * HD);
#pragma unroll
    for (int i = 0; i < 8; i++) q[i] = Qp[i];
    __syncthreads();

    const float* bT = g_biasT + (size_t)h * NN * NN + tid;

    float mx = -1e30f, l = 0.0f;
    float4 acc[8];
#pragma unroll
    for (int i = 0; i < 8; i++) acc[i] = make_float4(0.f, 0.f, 0.f, 0.f);

    for (int m0 = 0; m0 < NN; m0 += 4) {
        float bvals[4];
#pragma unroll
        for (int j = 0; j < 4; j++) bvals[j] = bT[(m0 + j) * NN];
#pragma unroll
        for (int j = 0; j < 4; j++) {
            int m = m0 + j;
            const float4* kr = (const float4*)(Ks + m * HD);
            float dot = 0.0f;
#pragma unroll
            for (int i = 0; i < 8; i++) {
                float4 kv = kr[i];
                dot += q[i].x * kv.x + q[i].y * kv.y + q[i].z * kv.z + q[i].w * kv.w;
            }
            float s = dot + bvals[j];
            float p;
            if (s > mx) {
                float corr = __expf(mx - s);
                l *= corr;
#pragma unroll
                for (int i = 0; i < 8; i++) {
                    acc[i].x *= corr; acc[i].y *= corr;
                    acc[i].z *= corr; acc[i].w *= corr;
                }
                mx = s;
                p = 1.0f;
            } else {
                p = __expf(s - mx);
            }
            l += p;
            const float4* vr = (const float4*)(Vs + m * HD);
#pragma unroll
            for (int i = 0; i < 8; i++) {
                float4 vv = vr[i];
                acc[i].x += p * vv.x; acc[i].y += p * vv.y;
                acc[i].z += p * vv.z; acc[i].w += p * vv.w;
            }
        }
    }

    float inv = 1.0f / l;
    float4* Op = (float4*)(g_AO + ((size_t)(b * NN + tid)) * NC + h * HD);
#pragma unroll
    for (int i = 0; i < 8; i++) {
        float4 o = acc[i];
        o.x *= inv; o.y *= inv; o.z *= inv; o.w *= inv;
        Op[i] = o;
    }
}

// ---------------------------------------------------------------------------
extern "C" void kernel_launch(void* const* d_in, const int* in_sizes, int n_in,
                              void* d_out, int out_size) {
    const float* x      = (const float*)d_in[0];
    const float* qkv_w  = (const float*)d_in[2];
    const float* qkv_b  = (const float*)d_in[3];
    const float* proj_w = (const float*)d_in[4];
    const float* proj_b = (const float*)d_in[5];
    const float* rpb    = (const float*)d_in[6];
    float* out = (float*)d_out;

    bias_kernel<<<(NH * NN * NN) / 256, 256>>>(rpb);

    // QKV: x[32768,512] @ qkv_w^T -> scatter Q/K/V
    mma_gemm<<<dim3(1536 / BN, (NB * NN) / BM), 256, GEMM_SMEM>>>(x, qkv_w, qkv_b, 0, nullptr);

    // Attention
    cudaFuncSetAttribute(attn_kernel, cudaFuncAttributeMaxDynamicSharedMemorySize,
                         2 * NN * HD * sizeof(float));
    attn_kernel<<<NB * NH, 256, 2 * NN * HD * sizeof(float)>>>();

    // Proj: g_AO[32768,512] @ proj_w^T -> out
    mma_gemm<<<dim3(NC / BN, (NB * NN) / BM), 256, GEMM_SMEM>>>(nullptr, proj_w, proj_b, 1, out);
}

// round 5
// speedup vs baseline: 2.4329x; 1.3691x over previous
#include <cuda_runtime.h>
#include <cstdint>
#include <math.h>

// Shapes (fixed)
#define NB 128
#define NN 256
#define NC 512
#define NH 16
#define HD 32
#define QSCALE 0.17677669529663687f  // 1/sqrt(32)
#define LOG2E  1.4426950408889634f

// GEMM tiling
#define BM 128
#define BN 128
#define BK 16
#define KSTRIDE 20
#define ABUF_FLOATS (BM * KSTRIDE)
#define GEMM_SMEM (4 * ABUF_FLOATS * 4)

// Attention smem layout (floats)
#define KS_STRIDE 36
#define VS_STRIDE 40
#define PST_STRIDE 68
#define KS_FLOATS (NN * KS_STRIDE)            // 9216
#define VS_FLOATS (NN * VS_STRIDE)            // 10240
#define PST_WARP (32 * PST_STRIDE)            // 2176
#define ATT_SMEM ((KS_FLOATS + VS_FLOATS + 8 * PST_WARP) * 4)  // 147456 B

// Scratch (device globals — no allocation allowed)
__device__ float g_Q[(size_t)NB * NH * NN * HD];   // pre-scaled by QSCALE*LOG2E
__device__ float g_K[(size_t)NB * NH * NN * HD];
__device__ float g_V[(size_t)NB * NH * NN * HD];
__device__ float g_biasT[(size_t)NH * NN * NN];    // [h][query][key], pre-scaled by LOG2E
__device__ float g_AO[(size_t)NB * NN * NC];

__device__ __forceinline__ uint32_t cvt_tf32(float f) {
    uint32_t u;
    asm("cvt.rna.tf32.f32 %0, %1;" : "=r"(u) : "f"(f));
    return u;
}
__device__ __forceinline__ void split_tf32(float f, uint32_t& hi, uint32_t& lo) {
    hi = cvt_tf32(f);
    lo = cvt_tf32(f - __uint_as_float(hi));
}
__device__ __forceinline__ void mma_tf32(float* d, const uint32_t* a, const uint32_t* b) {
    asm volatile(
        "mma.sync.aligned.m16n8k8.row.col.f32.tf32.tf32.f32 "
        "{%0,%1,%2,%3}, {%4,%5,%6,%7}, {%8,%9}, {%0,%1,%2,%3};"
        : "+f"(d[0]), "+f"(d[1]), "+f"(d[2]), "+f"(d[3])
        : "r"(a[0]), "r"(a[1]), "r"(a[2]), "r"(a[3]), "r"(b[0]), "r"(b[1]));
}

// ---------------------------------------------------------------------------
// Bias precompute: g_biasT[h][m=query][n=key] = rpb[idx(m,n)][h] * LOG2E
// idx(i,j) = (r_i - r_j + 7)*63 + (c_i - c_j + 31), r=tok/32, c=tok%32
// ---------------------------------------------------------------------------
__global__ void bias_kernel(const float* __restrict__ rpb) {
    int idx = blockIdx.x * blockDim.x + threadIdx.x;
    int n = idx & 255;          // key
    int m = (idx >> 8) & 255;   // query
    int h = idx >> 16;
    int t = ((m >> 5) - (n >> 5) + 7) * 63 + ((m & 31) - (n & 31) + 31);
    g_biasT[idx] = rpb[t * NH + h] * LOG2E;
}

// ---------------------------------------------------------------------------
// tf32 mma.sync GEMM (Q folds QSCALE*LOG2E)
// ---------------------------------------------------------------------------
__global__ __launch_bounds__(256, 2) void mma_gemm(const float* __restrict__ Ain,
                                                   const float* __restrict__ W,
                                                   const float* __restrict__ bias,
                                                   int mode, float* __restrict__ out) {
    extern __shared__ float sm[];
    const float* A = Ain ? Ain : (const float*)g_AO;

    int tid = threadIdx.x;
    int wid = tid >> 5;
    int lane = tid & 31;
    int wr = wid >> 2;
    int wc = wid & 3;
    int lr = lane >> 2;
    int lc = lane & 3;

    int row0 = blockIdx.y * BM;
    int col0 = blockIdx.x * BN;

    int r_g = tid >> 2;
    int c4_g = tid & 3;
    const float4* Ag0 = (const float4*)(A + (size_t)(row0 + r_g) * NC) + c4_g;
    const float4* Ag1 = (const float4*)(A + (size_t)(row0 + r_g + 64) * NC) + c4_g;
    const float4* Bg0 = (const float4*)(W + (size_t)(col0 + r_g) * NC) + c4_g;
    const float4* Bg1 = (const float4*)(W + (size_t)(col0 + r_g + 64) * NC) + c4_g;

    float acc[4][4][4];
#pragma unroll
    for (int i = 0; i < 4; i++)
#pragma unroll
        for (int j = 0; j < 4; j++)
#pragma unroll
            for (int k = 0; k < 4; k++) acc[i][j][k] = 0.0f;

    float4 ra0, ra1, rb0, rb1;
    ra0 = Ag0[0]; ra1 = Ag1[0]; rb0 = Bg0[0]; rb1 = Bg1[0];

    const int NCH = NC / BK;
#pragma unroll 1
    for (int c = 0; c < NCH; c++) {
        int cur = c & 1;
        {
            float* As = sm + cur * ABUF_FLOATS;
            float* Bs = sm + 2 * ABUF_FLOATS + cur * ABUF_FLOATS;
            uint4 u;
            u = make_uint4(cvt_tf32(ra0.x), cvt_tf32(ra0.y), cvt_tf32(ra0.z), cvt_tf32(ra0.w));
            *(uint4*)(As + r_g * KSTRIDE + c4_g * 4) = u;
            u = make_uint4(cvt_tf32(ra1.x), cvt_tf32(ra1.y), cvt_tf32(ra1.z), cvt_tf32(ra1.w));
            *(uint4*)(As + (r_g + 64) * KSTRIDE + c4_g * 4) = u;
            u = make_uint4(cvt_tf32(rb0.x), cvt_tf32(rb0.y), cvt_tf32(rb0.z), cvt_tf32(rb0.w));
            *(uint4*)(Bs + r_g * KSTRIDE + c4_g * 4) = u;
            u = make_uint4(cvt_tf32(rb1.x), cvt_tf32(rb1.y), cvt_tf32(rb1.z), cvt_tf32(rb1.w));
            *(uint4*)(Bs + (r_g + 64) * KSTRIDE + c4_g * 4) = u;
        }
        if (c + 1 < NCH) {
            int ko = (c + 1) * (BK / 4);
            ra0 = Ag0[ko]; ra1 = Ag1[ko]; rb0 = Bg0[ko]; rb1 = Bg1[ko];
        }
        __syncthreads();
        {
            const uint32_t* As = (const uint32_t*)(sm + cur * ABUF_FLOATS);
            const uint32_t* Bs = (const uint32_t*)(sm + 2 * ABUF_FLOATS + cur * ABUF_FLOATS);
#pragma unroll
            for (int ks = 0; ks < 2; ks++) {
                int k0 = ks * 8;
                uint32_t af[4][4], bf[4][2];
#pragma unroll
                for (int mt = 0; mt < 4; mt++) {
                    int r0 = wr * 64 + mt * 16 + lr;
                    af[mt][0] = As[r0 * KSTRIDE + k0 + lc];
                    af[mt][1] = As[(r0 + 8) * KSTRIDE + k0 + lc];
                    af[mt][2] = As[r0 * KSTRIDE + k0 + lc + 4];
                    af[mt][3] = As[(r0 + 8) * KSTRIDE + k0 + lc + 4];
                }
#pragma unroll
                for (int nt = 0; nt < 4; nt++) {
                    int n0 = wc * 32 + nt * 8 + lr;
                    bf[nt][0] = Bs[n0 * KSTRIDE + k0 + lc];
                    bf[nt][1] = Bs[n0 * KSTRIDE + k0 + lc + 4];
                }
#pragma unroll
                for (int mt = 0; mt < 4; mt++)
#pragma unroll
                    for (int nt = 0; nt < 4; nt++)
                        mma_tf32(acc[mt][nt], af[mt], bf[nt]);
            }
        }
        __syncthreads();
    }

    int colw = col0 + wc * 32;
    float bv[4][2];
#pragma unroll
    for (int nt = 0; nt < 4; nt++) {
        bv[nt][0] = bias[colw + nt * 8 + 2 * lc];
        bv[nt][1] = bias[colw + nt * 8 + 2 * lc + 1];
    }

    if (mode == 0) {
        int which = colw >> 9;
        float* dst = (which == 0) ? g_Q : ((which == 1) ? g_K : g_V);
        float qs = (which == 0) ? (QSCALE * LOG2E) : 1.0f;
        int h = (colw & 511) >> 5;
#pragma unroll
        for (int mt = 0; mt < 4; mt++) {
            int gr0 = row0 + wr * 64 + mt * 16 + lr;
            int b0i = gr0 >> 8, n0i = gr0 & 255;
            int gr1 = gr0 + 8;
            int b1i = gr1 >> 8, n1i = gr1 & 255;
            float* p0 = dst + (((size_t)b0i * NH + h) * NN + n0i) * HD;
            float* p1 = dst + (((size_t)b1i * NH + h) * NN + n1i) * HD;
#pragma unroll
            for (int nt = 0; nt < 4; nt++) {
                int d = nt * 8 + 2 * lc;
                *(float2*)(p0 + d) = make_float2((acc[mt][nt][0] + bv[nt][0]) * qs,
                                                 (acc[mt][nt][1] + bv[nt][1]) * qs);
                *(float2*)(p1 + d) = make_float2((acc[mt][nt][2] + bv[nt][0]) * qs,
                                                 (acc[mt][nt][3] + bv[nt][1]) * qs);
            }
        }
    } else {
#pragma unroll
        for (int mt = 0; mt < 4; mt++) {
            int gr0 = row0 + wr * 64 + mt * 16 + lr;
            float* p0 = out + (size_t)gr0 * NC + colw;
            float* p1 = out + (size_t)(gr0 + 8) * NC + colw;
#pragma unroll
            for (int nt = 0; nt < 4; nt++) {
                int d = nt * 8 + 2 * lc;
                *(float2*)(p0 + d) = make_float2(acc[mt][nt][0] + bv[nt][0],
                                                 acc[mt][nt][1] + bv[nt][1]);
                *(float2*)(p1 + d) = make_float2(acc[mt][nt][2] + bv[nt][0],
                                                 acc[mt][nt][3] + bv[nt][1]);
            }
        }
    }
}

// ---------------------------------------------------------------------------
// mma attention: one CTA per (b,h). 8 warps x 32 query rows. tf32x3 QK & PV,
// online softmax in exp2 domain. K/V in padded smem, P staged per-warp.
// ---------------------------------------------------------------------------
__global__ __launch_bounds__(256, 1) void attn_mma() {
    extern __shared__ float sm[];
    float* Ks = sm;
    float* Vs = sm + KS_FLOATS;
    int tid = threadIdx.x;
    int w = tid >> 5, lane = tid & 31;
    int lr = lane >> 2, lc = lane & 3;
    float* Pw = sm + KS_FLOATS + VS_FLOATS + w * PST_WARP;

    int bh = blockIdx.x;
    int b = bh >> 4, h = bh & 15;
    size_t base = (size_t)bh * NN * HD;

    // load K,V into padded smem
#pragma unroll
    for (int i = 0; i < 8; i++) {
        int idx = tid + i * 256;
        int row = idx >> 3, c4 = idx & 7;
        float4 kv = *(const float4*)(g_K + base + (size_t)row * HD + c4 * 4);
        *(float4*)(Ks + row * KS_STRIDE + c4 * 4) = kv;
        float4 vv = *(const float4*)(g_V + base + (size_t)row * HD + c4 * 4);
        *(float4*)(Vs + row * VS_STRIDE + c4 * 4) = vv;
    }

    // Q fragments (hi/lo tf32 split), warp owns rows [w*32, w*32+32)
    int m0 = w * 32;
    uint32_t ah[2][4][4], al[2][4][4];
    const float* Qb = g_Q + base;
#pragma unroll
    for (int mt = 0; mt < 2; mt++)
#pragma unroll
        for (int kt = 0; kt < 4; kt++) {
            int r0 = m0 + mt * 16 + lr;
            split_tf32(Qb[(size_t)r0 * HD + kt * 8 + lc],           ah[mt][kt][0], al[mt][kt][0]);
            split_tf32(Qb[(size_t)(r0 + 8) * HD + kt * 8 + lc],     ah[mt][kt][1], al[mt][kt][1]);
            split_tf32(Qb[(size_t)r0 * HD + kt * 8 + lc + 4],       ah[mt][kt][2], al[mt][kt][2]);
            split_tf32(Qb[(size_t)(r0 + 8) * HD + kt * 8 + lc + 4], ah[mt][kt][3], al[mt][kt][3]);
        }
    __syncthreads();

    const float* bT = g_biasT + (size_t)h * NN * NN;  // [query][key]

    float mx[4] = {-1e30f, -1e30f, -1e30f, -1e30f};
    float l[4] = {0.f, 0.f, 0.f, 0.f};
    float oacc[2][4][4];
#pragma unroll
    for (int mt = 0; mt < 2; mt++)
#pragma unroll
        for (int nt = 0; nt < 4; nt++)
#pragma unroll
            for (int k = 0; k < 4; k++) oacc[mt][nt][k] = 0.0f;

#pragma unroll 1
    for (int nb = 0; nb < 4; nb++) {
        int n0b = nb * 64;
        float sacc[2][8][4];
#pragma unroll
        for (int mt = 0; mt < 2; mt++)
#pragma unroll
            for (int nt = 0; nt < 8; nt++)
#pragma unroll
                for (int k = 0; k < 4; k++) sacc[mt][nt][k] = 0.0f;

        // --- QK^T (tf32x3) ---
#pragma unroll
        for (int nt = 0; nt < 8; nt++) {
            int nrow = n0b + nt * 8 + lr;
#pragma unroll
            for (int kt = 0; kt < 4; kt++) {
                uint32_t bh0, bl0, bh1, bl1;
                split_tf32(Ks[nrow * KS_STRIDE + kt * 8 + lc], bh0, bl0);
                split_tf32(Ks[nrow * KS_STRIDE + kt * 8 + lc + 4], bh1, bl1);
                uint32_t bhv[2] = {bh0, bh1}, blv[2] = {bl0, bl1};
                mma_tf32(sacc[0][nt], ah[0][kt], bhv);
                mma_tf32(sacc[1][nt], ah[1][kt], bhv);
                mma_tf32(sacc[0][nt], al[0][kt], bhv);
                mma_tf32(sacc[1][nt], al[1][kt], bhv);
                mma_tf32(sacc[0][nt], ah[0][kt], blv);
                mma_tf32(sacc[1][nt], ah[1][kt], blv);
            }
        }

        // --- bias add ([query][key] layout) ---
#pragma unroll
        for (int mt = 0; mt < 2; mt++) {
            int r0 = m0 + mt * 16 + lr;
#pragma unroll
            for (int nt = 0; nt < 8; nt++) {
                int n = n0b + nt * 8 + 2 * lc;
                float2 b0 = *(const float2*)(bT + (size_t)r0 * NN + n);
                float2 b1 = *(const float2*)(bT + (size_t)(r0 + 8) * NN + n);
                sacc[mt][nt][0] += b0.x; sacc[mt][nt][1] += b0.y;
                sacc[mt][nt][2] += b1.x; sacc[mt][nt][3] += b1.y;
            }
        }

        // --- online softmax (exp2 domain) ---
#pragma unroll
        for (int mt = 0; mt < 2; mt++)
#pragma unroll
            for (int hf = 0; hf < 2; hf++) {
                int r = mt * 2 + hf;
                float vmax = -1e30f;
#pragma unroll
                for (int nt = 0; nt < 8; nt++)
                    vmax = fmaxf(vmax, fmaxf(sacc[mt][nt][hf * 2], sacc[mt][nt][hf * 2 + 1]));
                vmax = fmaxf(vmax, __shfl_xor_sync(0xffffffffu, vmax, 1));
                vmax = fmaxf(vmax, __shfl_xor_sync(0xffffffffu, vmax, 2));
                float nmx = fmaxf(mx[r], vmax);
                float fct = exp2f(mx[r] - nmx);
                mx[r] = nmx;
                l[r] *= fct;
#pragma unroll
                for (int nt = 0; nt < 4; nt++) {
                    oacc[mt][nt][hf * 2] *= fct;
                    oacc[mt][nt][hf * 2 + 1] *= fct;
                }
                float rs = 0.f;
#pragma unroll
                for (int nt = 0; nt < 8; nt++) {
                    float p0 = exp2f(sacc[mt][nt][hf * 2] - nmx);
                    float p1 = exp2f(sacc[mt][nt][hf * 2 + 1] - nmx);
                    sacc[mt][nt][hf * 2] = p0;
                    sacc[mt][nt][hf * 2 + 1] = p1;
                    rs += p0 + p1;
                }
                rs += __shfl_xor_sync(0xffffffffu, rs, 1);
                rs += __shfl_xor_sync(0xffffffffu, rs, 2);
                l[r] += rs;
            }

        // --- stage P (acc layout -> A-operand layout via smem) ---
#pragma unroll
        for (int mt = 0; mt < 2; mt++)
#pragma unroll
            for (int nt = 0; nt < 8; nt++) {
                *(float2*)(Pw + (mt * 16 + lr) * PST_STRIDE + nt * 8 + 2 * lc) =
                    make_float2(sacc[mt][nt][0], sacc[mt][nt][1]);
                *(float2*)(Pw + (mt * 16 + lr + 8) * PST_STRIDE + nt * 8 + 2 * lc) =
                    make_float2(sacc[mt][nt][2], sacc[mt][nt][3]);
            }
        __syncwarp();

        // --- P·V (tf32x3) ---
#pragma unroll
        for (int kt = 0; kt < 8; kt++) {
            int k0 = kt * 8;
            uint32_t ph[2][4], pl[2][4];
#pragma unroll
            for (int mt = 0; mt < 2; mt++) {
                split_tf32(Pw[(mt * 16 + lr) * PST_STRIDE + k0 + lc],         ph[mt][0], pl[mt][0]);
                split_tf32(Pw[(mt * 16 + lr + 8) * PST_STRIDE + k0 + lc],     ph[mt][1], pl[mt][1]);
                split_tf32(Pw[(mt * 16 + lr) * PST_STRIDE + k0 + lc + 4],     ph[mt][2], pl[mt][2]);
                split_tf32(Pw[(mt * 16 + lr + 8) * PST_STRIDE + k0 + lc + 4], ph[mt][3], pl[mt][3]);
            }
            int krow0 = n0b + k0 + lc;
            int krow1 = krow0 + 4;
#pragma unroll
            for (int nt = 0; nt < 4; nt++) {
                uint32_t vh[2], vl[2];
                split_tf32(Vs[krow0 * VS_STRIDE + nt * 8 + lr], vh[0], vl[0]);
                split_tf32(Vs[krow1 * VS_STRIDE + nt * 8 + lr], vh[1], vl[1]);
                mma_tf32(oacc[0][nt], ph[0], vh);
                mma_tf32(oacc[1][nt], ph[1], vh);
                mma_tf32(oacc[0][nt], pl[0], vh);
                mma_tf32(oacc[1][nt], pl[1], vh);
                mma_tf32(oacc[0][nt], ph[0], vl);
                mma_tf32(oacc[1][nt], ph[1], vl);
            }
        }
        __syncwarp();
    }

    // epilogue: normalize and write [B,N,C] slice
    float* AObase = g_AO + (size_t)b * NN * NC + h * HD;
#pragma unroll
    for (int mt = 0; mt < 2; mt++) {
        int r0 = m0 + mt * 16 + lr;
        float inv0 = 1.0f / l[mt * 2];
        float inv1 = 1.0f / l[mt * 2 + 1];
#pragma unroll
        for (int nt = 0; nt < 4; nt++) {
            int d = nt * 8 + 2 * lc;
            *(float2*)(AObase + (size_t)r0 * NC + d) =
                make_float2(oacc[mt][nt][0] * inv0, oacc[mt][nt][1] * inv0);
            *(float2*)(AObase + (size_t)(r0 + 8) * NC + d) =
                make_float2(oacc[mt][nt][2] * inv1, oacc[mt][nt][3] * inv1);
        }
    }
}

// ---------------------------------------------------------------------------
extern "C" void kernel_launch(void* const* d_in, const int* in_sizes, int n_in,
                              void* d_out, int out_size) {
    const float* x      = (const float*)d_in[0];
    const float* qkv_w  = (const float*)d_in[2];
    const float* qkv_b  = (const float*)d_in[3];
    const float* proj_w = (const float*)d_in[4];
    const float* proj_b = (const float*)d_in[5];
    const float* rpb    = (const float*)d_in[6];
    float* out = (float*)d_out;

    bias_kernel<<<(NH * NN * NN) / 256, 256>>>(rpb);

    mma_gemm<<<dim3(1536 / BN, (NB * NN) / BM), 256, GEMM_SMEM>>>(x, qkv_w, qkv_b, 0, nullptr);

    cudaFuncSetAttribute(attn_mma, cudaFuncAttributeMaxDynamicSharedMemorySize, ATT_SMEM);
    attn_mma<<<NB * NH, 256, ATT_SMEM>>>();

    mma_gemm<<<dim3(NC / BN, (NB * NN) / BM), 256, GEMM_SMEM>>>(nullptr, proj_w, proj_b, 1, out);
}

// round 6
// speedup vs baseline: 2.7642x; 1.1362x over previous
#include <cuda_runtime.h>
#include <cstdint>
#include <math.h>

// Shapes (fixed)
#define NB 128
#define NN 256
#define NC 512
#define NH 16
#define HD 32
#define QSCALE 0.17677669529663687f  // 1/sqrt(32)
#define LOG2E  1.4426950408889634f

// GEMM tiling
#define BM 128
#define BN 128
#define BK 16
#define KSTRIDE 20
#define ABUF_FLOATS (BM * KSTRIDE)       // 2560
#define GEMM_SMEM (4 * ABUF_FLOATS * 4)  // 40960 B

// Attention smem layout (floats)
#define KS_STRIDE 36
#define VS_STRIDE 40
#define PST_STRIDE 68
#define KS_FLOATS (NN * KS_STRIDE)
#define VS_FLOATS (NN * VS_STRIDE)
#define PST_WARP (32 * PST_STRIDE)
#define ATT_SMEM ((KS_FLOATS + VS_FLOATS + 8 * PST_WARP) * 4)

// Scratch (device globals — no allocation allowed)
__device__ float g_Q[(size_t)NB * NH * NN * HD];   // pre-scaled by QSCALE*LOG2E
__device__ float g_K[(size_t)NB * NH * NN * HD];
__device__ float g_V[(size_t)NB * NH * NN * HD];
__device__ float g_biasT[(size_t)NH * NN * NN];    // [h][query][key], * LOG2E
__device__ float g_AO[(size_t)NB * NN * NC];

__device__ __forceinline__ uint32_t cvt_tf32(float f) {
    uint32_t u;
    asm("cvt.rna.tf32.f32 %0, %1;" : "=r"(u) : "f"(f));
    return u;
}
__device__ __forceinline__ void split_tf32(float f, uint32_t& hi, uint32_t& lo) {
    hi = cvt_tf32(f);
    lo = cvt_tf32(f - __uint_as_float(hi));
}
__device__ __forceinline__ void mma_tf32(float* d, const uint32_t* a, const uint32_t* b) {
    asm volatile(
        "mma.sync.aligned.m16n8k8.row.col.f32.tf32.tf32.f32 "
        "{%0,%1,%2,%3}, {%4,%5,%6,%7}, {%8,%9}, {%0,%1,%2,%3};"
        : "+f"(d[0]), "+f"(d[1]), "+f"(d[2]), "+f"(d[3])
        : "r"(a[0]), "r"(a[1]), "r"(a[2]), "r"(a[3]), "r"(b[0]), "r"(b[1]));
}

// ---------------------------------------------------------------------------
// Bias precompute: g_biasT[h][m=query][n=key] = rpb[idx(m,n)][h] * LOG2E
// ---------------------------------------------------------------------------
__global__ void bias_kernel(const float* __restrict__ rpb) {
    int idx = blockIdx.x * blockDim.x + threadIdx.x;
    int n = idx & 255;          // key
    int m = (idx >> 8) & 255;   // query
    int h = idx >> 16;
    int t = ((m >> 5) - (n >> 5) + 7) * 63 + ((m & 31) - (n & 31) + 31);
    g_biasT[idx] = rpb[t * NH + h] * LOG2E;
}

// ---------------------------------------------------------------------------
// tf32 mma.sync GEMM, 128 threads, 4 warps (2x2), warp tile 64x64.
// D[m][n] = sum_k A[m][k]*W[n][k]; Q folds QSCALE*LOG2E.
// ---------------------------------------------------------------------------
__global__ __launch_bounds__(128, 2) void mma_gemm(const float* __restrict__ Ain,
                                                   const float* __restrict__ W,
                                                   const float* __restrict__ bias,
                                                   int mode, float* __restrict__ out) {
    extern __shared__ float sm[];
    const float* A = Ain ? Ain : (const float*)g_AO;

    int tid = threadIdx.x;
    int wid = tid >> 5;
    int lane = tid & 31;
    int wr = wid >> 1;        // 0..1 (64-row group)
    int wc = wid & 1;         // 0..1 (64-col group)
    int lr = lane >> 2;       // 0..7
    int lc = lane & 3;        // 0..3

    int row0 = blockIdx.y * BM;
    int col0 = blockIdx.x * BN;

    // gmem mapping: thread handles float4 slots {i*128 + tid}, i=0..3
    int rb = tid >> 2;        // 0..31 (row base; +i*32)
    int c4 = tid & 3;
    const float4* Ag = (const float4*)(A + (size_t)(row0 + rb) * NC) + c4;
    const float4* Bg = (const float4*)(W + (size_t)(col0 + rb) * NC) + c4;
    const size_t gstep = (size_t)32 * NC / 4;   // 32 rows in float4 units

    float acc[4][8][4];
#pragma unroll
    for (int i = 0; i < 4; i++)
#pragma unroll
        for (int j = 0; j < 8; j++)
#pragma unroll
            for (int k = 0; k < 4; k++) acc[i][j][k] = 0.0f;

    float4 sa[4], sb[4];
#pragma unroll
    for (int i = 0; i < 4; i++) {
        sa[i] = Ag[i * gstep];
        sb[i] = Bg[i * gstep];
    }

    const int NCH = NC / BK;  // 32
#pragma unroll 1
    for (int c = 0; c < NCH; c++) {
        int cur = c & 1;
        float* As = sm + cur * ABUF_FLOATS;
        float* Bs = sm + 2 * ABUF_FLOATS + cur * ABUF_FLOATS;
#pragma unroll
        for (int i = 0; i < 4; i++) {
            int r = rb + i * 32;
            *(uint4*)(As + r * KSTRIDE + c4 * 4) =
                make_uint4(cvt_tf32(sa[i].x), cvt_tf32(sa[i].y), cvt_tf32(sa[i].z), cvt_tf32(sa[i].w));
            *(uint4*)(Bs + r * KSTRIDE + c4 * 4) =
                make_uint4(cvt_tf32(sb[i].x), cvt_tf32(sb[i].y), cvt_tf32(sb[i].z), cvt_tf32(sb[i].w));
        }
        if (c + 1 < NCH) {
            size_t ko = (size_t)(c + 1) * (BK / 4);
#pragma unroll
            for (int i = 0; i < 4; i++) {
                sa[i] = Ag[i * gstep + ko];
                sb[i] = Bg[i * gstep + ko];
            }
        }
        __syncthreads();
        {
            const uint32_t* Asu = (const uint32_t*)As;
            const uint32_t* Bsu = (const uint32_t*)Bs;
#pragma unroll
            for (int ks = 0; ks < 2; ks++) {
                int k0 = ks * 8;
                uint32_t af[4][4], bf[8][2];
#pragma unroll
                for (int mt = 0; mt < 4; mt++) {
                    int r0 = wr * 64 + mt * 16 + lr;
                    af[mt][0] = Asu[r0 * KSTRIDE + k0 + lc];
                    af[mt][1] = Asu[(r0 + 8) * KSTRIDE + k0 + lc];
                    af[mt][2] = Asu[r0 * KSTRIDE + k0 + lc + 4];
                    af[mt][3] = Asu[(r0 + 8) * KSTRIDE + k0 + lc + 4];
                }
#pragma unroll
                for (int nt = 0; nt < 8; nt++) {
                    int n0 = wc * 64 + nt * 8 + lr;
                    bf[nt][0] = Bsu[n0 * KSTRIDE + k0 + lc];
                    bf[nt][1] = Bsu[n0 * KSTRIDE + k0 + lc + 4];
                }
#pragma unroll
                for (int mt = 0; mt < 4; mt++)
#pragma unroll
                    for (int nt = 0; nt < 8; nt++)
                        mma_tf32(acc[mt][nt], af[mt], bf[nt]);
            }
        }
        // NOTE: single barrier per chunk — the next STS targets the other
        // buffer; the one after that is ordered behind the next barrier.
    }

    // -------------------------- epilogue --------------------------
    int colw = col0 + wc * 64;   // warp's 64-col span (aligned: no 512-straddle)
    float bv[8][2];
#pragma unroll
    for (int nt = 0; nt < 8; nt++) {
        bv[nt][0] = bias[colw + nt * 8 + 2 * lc];
        bv[nt][1] = bias[colw + nt * 8 + 2 * lc + 1];
    }

    if (mode == 0) {
        int which = colw >> 9;
        float* dst = (which == 0) ? g_Q : ((which == 1) ? g_K : g_V);
        float qs = (which == 0) ? (QSCALE * LOG2E) : 1.0f;
        int hbase = (colw & 511) >> 5;   // warp spans heads hbase, hbase+1
#pragma unroll
        for (int mt = 0; mt < 4; mt++) {
            int gr0 = row0 + wr * 64 + mt * 16 + lr;
            int b0i = gr0 >> 8, n0i = gr0 & 255;
            int gr1 = gr0 + 8;
            int b1i = gr1 >> 8, n1i = gr1 & 255;
            float* p0 = dst + (((size_t)b0i * NH + hbase) * NN + n0i) * HD;
            float* p1 = dst + (((size_t)b1i * NH + hbase) * NN + n1i) * HD;
#pragma unroll
            for (int nt = 0; nt < 8; nt++) {
                int hofs = (nt >> 2) * NN * HD;   // second head: +NN*HD
                int d = (nt & 3) * 8 + 2 * lc;
                *(float2*)(p0 + hofs + d) =
                    make_float2((acc[mt][nt][0] + bv[nt][0]) * qs,
                                (acc[mt][nt][1] + bv[nt][1]) * qs);
                *(float2*)(p1 + hofs + d) =
                    make_float2((acc[mt][nt][2] + bv[nt][0]) * qs,
                                (acc[mt][nt][3] + bv[nt][1]) * qs);
            }
        }
    } else {
#pragma unroll
        for (int mt = 0; mt < 4; mt++) {
            int gr0 = row0 + wr * 64 + mt * 16 + lr;
            float* p0 = out + (size_t)gr0 * NC + colw;
            float* p1 = out + (size_t)(gr0 + 8) * NC + colw;
#pragma unroll
            for (int nt = 0; nt < 8; nt++) {
                int d = nt * 8 + 2 * lc;
                *(float2*)(p0 + d) = make_float2(acc[mt][nt][0] + bv[nt][0],
                                                 acc[mt][nt][1] + bv[nt][1]);
                *(float2*)(p1 + d) = make_float2(acc[mt][nt][2] + bv[nt][0],
                                                 acc[mt][nt][3] + bv[nt][1]);
            }
        }
    }
}

// ---------------------------------------------------------------------------
// mma attention: one CTA per (b,h). 8 warps x 32 query rows. tf32x3 QK & PV,
// online softmax in exp2 domain. (unchanged from R5)
// ---------------------------------------------------------------------------
__global__ __launch_bounds__(256, 1) void attn_mma() {
    extern __shared__ float sm[];
    float* Ks = sm;
    float* Vs = sm + KS_FLOATS;
    int tid = threadIdx.x;
    int w = tid >> 5, lane = tid & 31;
    int lr = lane >> 2, lc = lane & 3;
    float* Pw = sm + KS_FLOATS + VS_FLOATS + w * PST_WARP;

    int bh = blockIdx.x;
    int b = bh >> 4, h = bh & 15;
    size_t base = (size_t)bh * NN * HD;

#pragma unroll
    for (int i = 0; i < 8; i++) {
        int idx = tid + i * 256;
        int row = idx >> 3, c4 = idx & 7;
        float4 kv = *(const float4*)(g_K + base + (size_t)row * HD + c4 * 4);
        *(float4*)(Ks + row * KS_STRIDE + c4 * 4) = kv;
        float4 vv = *(const float4*)(g_V + base + (size_t)row * HD + c4 * 4);
        *(float4*)(Vs + row * VS_STRIDE + c4 * 4) = vv;
    }

    int m0 = w * 32;
    uint32_t ah[2][4][4], al[2][4][4];
    const float* Qb = g_Q + base;
#pragma unroll
    for (int mt = 0; mt < 2; mt++)
#pragma unroll
        for (int kt = 0; kt < 4; kt++) {
            int r0 = m0 + mt * 16 + lr;
            split_tf32(Qb[(size_t)r0 * HD + kt * 8 + lc],           ah[mt][kt][0], al[mt][kt][0]);
            split_tf32(Qb[(size_t)(r0 + 8) * HD + kt * 8 + lc],     ah[mt][kt][1], al[mt][kt][1]);
            split_tf32(Qb[(size_t)r0 * HD + kt * 8 + lc + 4],       ah[mt][kt][2], al[mt][kt][2]);
            split_tf32(Qb[(size_t)(r0 + 8) * HD + kt * 8 + lc + 4], ah[mt][kt][3], al[mt][kt][3]);
        }
    __syncthreads();

    const float* bT = g_biasT + (size_t)h * NN * NN;

    float mx[4] = {-1e30f, -1e30f, -1e30f, -1e30f};
    float l[4] = {0.f, 0.f, 0.f, 0.f};
    float oacc[2][4][4];
#pragma unroll
    for (int mt = 0; mt < 2; mt++)
#pragma unroll
        for (int nt = 0; nt < 4; nt++)
#pragma unroll
            for (int k = 0; k < 4; k++) oacc[mt][nt][k] = 0.0f;

#pragma unroll 1
    for (int nb = 0; nb < 4; nb++) {
        int n0b = nb * 64;
        float sacc[2][8][4];
#pragma unroll
        for (int mt = 0; mt < 2; mt++)
#pragma unroll
            for (int nt = 0; nt < 8; nt++)
#pragma unroll
                for (int k = 0; k < 4; k++) sacc[mt][nt][k] = 0.0f;

#pragma unroll
        for (int nt = 0; nt < 8; nt++) {
            int nrow = n0b + nt * 8 + lr;
#pragma unroll
            for (int kt = 0; kt < 4; kt++) {
                uint32_t bh0, bl0, bh1, bl1;
                split_tf32(Ks[nrow * KS_STRIDE + kt * 8 + lc], bh0, bl0);
                split_tf32(Ks[nrow * KS_STRIDE + kt * 8 + lc + 4], bh1, bl1);
                uint32_t bhv[2] = {bh0, bh1}, blv[2] = {bl0, bl1};
                mma_tf32(sacc[0][nt], ah[0][kt], bhv);
                mma_tf32(sacc[1][nt], ah[1][kt], bhv);
                mma_tf32(sacc[0][nt], al[0][kt], bhv);
                mma_tf32(sacc[1][nt], al[1][kt], bhv);
                mma_tf32(sacc[0][nt], ah[0][kt], blv);
                mma_tf32(sacc[1][nt], ah[1][kt], blv);
            }
        }

#pragma unroll
        for (int mt = 0; mt < 2; mt++) {
            int r0 = m0 + mt * 16 + lr;
#pragma unroll
            for (int nt = 0; nt < 8; nt++) {
                int n = n0b + nt * 8 + 2 * lc;
                float2 b0 = *(const float2*)(bT + (size_t)r0 * NN + n);
                float2 b1 = *(const float2*)(bT + (size_t)(r0 + 8) * NN + n);
                sacc[mt][nt][0] += b0.x; sacc[mt][nt][1] += b0.y;
                sacc[mt][nt][2] += b1.x; sacc[mt][nt][3] += b1.y;
            }
        }

#pragma unroll
        for (int mt = 0; mt < 2; mt++)
#pragma unroll
            for (int hf = 0; hf < 2; hf++) {
                int r = mt * 2 + hf;
                float vmax = -1e30f;
#pragma unroll
                for (int nt = 0; nt < 8; nt++)
                    vmax = fmaxf(vmax, fmaxf(sacc[mt][nt][hf * 2], sacc[mt][nt][hf * 2 + 1]));
                vmax = fmaxf(vmax, __shfl_xor_sync(0xffffffffu, vmax, 1));
                vmax = fmaxf(vmax, __shfl_xor_sync(0xffffffffu, vmax, 2));
                float nmx = fmaxf(mx[r], vmax);
                float fct = exp2f(mx[r] - nmx);
                mx[r] = nmx;
                l[r] *= fct;
#pragma unroll
                for (int nt = 0; nt < 4; nt++) {
                    oacc[mt][nt][hf * 2] *= fct;
                    oacc[mt][nt][hf * 2 + 1] *= fct;
                }
                float rs = 0.f;
#pragma unroll
                for (int nt = 0; nt < 8; nt++) {
                    float p0 = exp2f(sacc[mt][nt][hf * 2] - nmx);
                    float p1 = exp2f(sacc[mt][nt][hf * 2 + 1] - nmx);
                    sacc[mt][nt][hf * 2] = p0;
                    sacc[mt][nt][hf * 2 + 1] = p1;
                    rs += p0 + p1;
                }
                rs += __shfl_xor_sync(0xffffffffu, rs, 1);
                rs += __shfl_xor_sync(0xffffffffu, rs, 2);
                l[r] += rs;
            }

#pragma unroll
        for (int mt = 0; mt < 2; mt++)
#pragma unroll
            for (int nt = 0; nt < 8; nt++) {
                *(float2*)(Pw + (mt * 16 + lr) * PST_STRIDE + nt * 8 + 2 * lc) =
                    make_float2(sacc[mt][nt][0], sacc[mt][nt][1]);
                *(float2*)(Pw + (mt * 16 + lr + 8) * PST_STRIDE + nt * 8 + 2 * lc) =
                    make_float2(sacc[mt][nt][2], sacc[mt][nt][3]);
            }
        __syncwarp();

#pragma unroll
        for (int kt = 0; kt < 8; kt++) {
            int k0 = kt * 8;
            uint32_t ph[2][4], pl[2][4];
#pragma unroll
            for (int mt = 0; mt < 2; mt++) {
                split_tf32(Pw[(mt * 16 + lr) * PST_STRIDE + k0 + lc],         ph[mt][0], pl[mt][0]);
                split_tf32(Pw[(mt * 16 + lr + 8) * PST_STRIDE + k0 + lc],     ph[mt][1], pl[mt][1]);
                split_tf32(Pw[(mt * 16 + lr) * PST_STRIDE + k0 + lc + 4],     ph[mt][2], pl[mt][2]);
                split_tf32(Pw[(mt * 16 + lr + 8) * PST_STRIDE + k0 + lc + 4], ph[mt][3], pl[mt][3]);
            }
            int krow0 = n0b + k0 + lc;
            int krow1 = krow0 + 4;
#pragma unroll
            for (int nt = 0; nt < 4; nt++) {
                uint32_t vh[2], vl[2];
                split_tf32(Vs[krow0 * VS_STRIDE + nt * 8 + lr], vh[0], vl[0]);
                split_tf32(Vs[krow1 * VS_STRIDE + nt * 8 + lr], vh[1], vl[1]);
                mma_tf32(oacc[0][nt], ph[0], vh);
                mma_tf32(oacc[1][nt], ph[1], vh);
                mma_tf32(oacc[0][nt], pl[0], vh);
                mma_tf32(oacc[1][nt], pl[1], vh);
                mma_tf32(oacc[0][nt], ph[0], vl);
                mma_tf32(oacc[1][nt], ph[1], vl);
            }
        }
        __syncwarp();
    }

    float* AObase = g_AO + (size_t)b * NN * NC + h * HD;
#pragma unroll
    for (int mt = 0; mt < 2; mt++) {
        int r0 = m0 + mt * 16 + lr;
        float inv0 = 1.0f / l[mt * 2];
        float inv1 = 1.0f / l[mt * 2 + 1];
#pragma unroll
        for (int nt = 0; nt < 4; nt++) {
            int d = nt * 8 + 2 * lc;
            *(float2*)(AObase + (size_t)r0 * NC + d) =
                make_float2(oacc[mt][nt][0] * inv0, oacc[mt][nt][1] * inv0);
            *(float2*)(AObase + (size_t)(r0 + 8) * NC + d) =
                make_float2(oacc[mt][nt][2] * inv1, oacc[mt][nt][3] * inv1);
        }
    }
}

// ---------------------------------------------------------------------------
extern "C" void kernel_launch(void* const* d_in, const int* in_sizes, int n_in,
                              void* d_out, int out_size) {
    const float* x      = (const float*)d_in[0];
    const float* qkv_w  = (const float*)d_in[2];
    const float* qkv_b  = (const float*)d_in[3];
    const float* proj_w = (const float*)d_in[4];
    const float* proj_b = (const float*)d_in[5];
    const float* rpb    = (const float*)d_in[6];
    float* out = (float*)d_out;

    bias_kernel<<<(NH * NN * NN) / 256, 256>>>(rpb);

    mma_gemm<<<dim3(1536 / BN, (NB * NN) / BM), 128, GEMM_SMEM>>>(x, qkv_w, qkv_b, 0, nullptr);

    cudaFuncSetAttribute(attn_mma, cudaFuncAttributeMaxDynamicSharedMemorySize, ATT_SMEM);
    attn_mma<<<NB * NH, 256, ATT_SMEM>>>();

    mma_gemm<<<dim3(NC / BN, (NB * NN) / BM), 128, GEMM_SMEM>>>(nullptr, proj_w, proj_b, 1, out);
}